// round 3
// baseline (speedup 1.0000x reference)
#include <cuda_runtime.h>
#include <math.h>

// Problem constants
#define BB   256
#define TT   512
#define DIN  64
#define HH   1024
#define DOUT 10

// Kernel config
#define GRID     128
#define NTHREADS 256
#define BT 64          // batch rows per CTA
#define HT 32          // h outputs per CTA
#define NH (HH/HT)     // 32 h-tiles
#define KC 64          // K chunk
#define NCHUNK (HH/KC) // 16

// SMEM layout (float offsets). Padded strides for conflict-free mma-frag LDS.
#define WHH_STRIDE 1028
#define XS_STRIDE  68
#define WHH_OFF  0
#define WHH_SZ   (HT*WHH_STRIDE)          // 32896
#define WHX_OFF  (WHH_OFF+WHH_SZ)
#define WHX_SZ   (HT*XS_STRIDE)           // 2176
#define BIAS_OFF (WHX_OFF+WHX_SZ)
#define BIAS_SZ  32
#define XS_OFF   (BIAS_OFF+BIAS_SZ)
#define XS_SZ    (BT*XS_STRIDE)           // 4352
#define HS_OFF   (XS_OFF+XS_SZ)
#define HS_SZ    (BT*XS_STRIDE)           // per buffer
#define SMEM_FLOATS (HS_OFF + 2*HS_SZ)    // 48160 floats
#define SMEM_BYTES  (SMEM_FLOATS*4)       // 192640 B

// Spin-bound: converts a (should-be-impossible) barrier deadlock into a fast,
// visibly-wrong answer instead of a 600s container kill.
#define SPIN_BOUND (1u << 22)

// Global scratch (allocation-free rule: __device__ globals)
__device__ float    g_h[2][BB*HH];   // double-buffered hidden state (tf32-rounded fp32)
__device__ unsigned g_bar[TT];       // per-step barrier counters (monotone, zeroed per launch)

// ---------- helpers ----------
__device__ __forceinline__ float to_tf32(float v) {
    unsigned u;
    asm("cvt.rna.tf32.f32 %0, %1;" : "=r"(u) : "f"(v));
    return __uint_as_float(u);
}

__device__ __forceinline__ void cp_async16(void* sptr, const void* gptr) {
    unsigned saddr = (unsigned)__cvta_generic_to_shared(sptr);
    asm volatile("cp.async.cg.shared.global [%0], [%1], 16;" :: "r"(saddr), "l"(gptr));
}
__device__ __forceinline__ void cp_commit() {
    asm volatile("cp.async.commit_group;");
}
template<int N> __device__ __forceinline__ void cp_wait() {
    asm volatile("cp.async.wait_group %0;" :: "n"(N));
}

__device__ __forceinline__ void mma_tf32(float* c, const unsigned* a, const unsigned* b) {
    asm volatile(
        "mma.sync.aligned.m16n8k8.row.col.f32.tf32.tf32.f32 "
        "{%0,%1,%2,%3}, {%4,%5,%6,%7}, {%8,%9}, {%0,%1,%2,%3};"
        : "+f"(c[0]), "+f"(c[1]), "+f"(c[2]), "+f"(c[3])
        : "r"(a[0]), "r"(a[1]), "r"(a[2]), "r"(a[3]),
          "r"(b[0]), "r"(b[1]));
}

// ---------- init: zero h0 and barrier counters (every launch -> graph-replay safe) ----------
__global__ void rnn_init_kernel() {
    int i = blockIdx.x * blockDim.x + threadIdx.x;
    if (i < BB*HH) g_h[0][i] = 0.0f;
    if (i < TT)    g_bar[i] = 0u;
}

// ---------- persistent RNN kernel ----------
__global__ void __launch_bounds__(NTHREADS, 1)
rnn_persistent_kernel(const float* __restrict__ x,
                      const float* __restrict__ Whx,
                      const float* __restrict__ Whh,
                      const float* __restrict__ bh,
                      const float* __restrict__ Why,
                      const float* __restrict__ by,
                      float* __restrict__ out)
{
    extern __shared__ float sm[];
    float* whh_s  = sm + WHH_OFF;
    float* whx_s  = sm + WHX_OFF;
    float* bias_s = sm + BIAS_OFF;
    float* x_s    = sm + XS_OFF;
    float* h_s0   = sm + HS_OFF;
    float* h_s1   = sm + HS_OFF + HS_SZ;

    const int tid = threadIdx.x;
    const int cta = blockIdx.x;
    const int jb = cta & (NH - 1);   // h tile index 0..31
    const int ib = cta >> 5;         // b tile index 0..3
    const int h_base = jb * HT;
    const int b_base = ib * BT;

    // Stage Whh slice [HT,1024] and Whx slice [HT,64] as tf32-rounded fp32 (once).
    for (int i = tid; i < HT*HH; i += NTHREADS) {
        int r = i >> 10, c = i & (HH - 1);
        whh_s[r*WHH_STRIDE + c] = to_tf32(Whh[(h_base + r)*HH + c]);
    }
    for (int i = tid; i < HT*DIN; i += NTHREADS) {
        int r = i >> 6, c = i & (DIN - 1);
        whx_s[r*XS_STRIDE + c] = to_tf32(Whx[(h_base + r)*DIN + c]);
    }
    if (tid < HT) bias_s[tid] = bh[h_base + tid];
    __syncthreads();

    const int warp = tid >> 5, lane = tid & 31;
    const int grp = lane >> 2, thr4 = lane & 3;
    const int wm = (warp >> 1) * 16;  // warp row offset: 0,16,32,48
    const int wn = (warp & 1) * 16;   // warp col offset: 0,16

    for (int t = 0; t < TT; ++t) {
        const float* hsrc = g_h[t & 1];
        float*       hdst = g_h[(t + 1) & 1];

        // Stage x_t tile + h chunk 0 (one cp.async group)
        {
            const float* xb = x + ((size_t)b_base * TT + t) * DIN;
            for (int i = tid; i < (BT*DIN)/4; i += NTHREADS) {  // 1024 x float4
                int r = i >> 4, q = i & 15;
                cp_async16(x_s + r*XS_STRIDE + q*4, xb + (size_t)r*TT*DIN + q*4);
            }
            for (int i = tid; i < (BT*KC)/4; i += NTHREADS) {
                int r = i >> 4, q = i & 15;
                cp_async16(h_s0 + r*XS_STRIDE + q*4, hsrc + (b_base + r)*HH + q*4);
            }
            cp_commit();
        }

        float acc0[4] = {0.f,0.f,0.f,0.f};
        float acc1[4] = {0.f,0.f,0.f,0.f};

        for (int c = 0; c < NCHUNK; ++c) {
            if (c + 1 < NCHUNK) {
                float* dst = (c & 1) ? h_s0 : h_s1;  // buffer (c+1)&1
                const float* src = hsrc + (c + 1)*KC;
                for (int i = tid; i < (BT*KC)/4; i += NTHREADS) {
                    int r = i >> 4, q = i & 15;
                    cp_async16(dst + r*XS_STRIDE + q*4, src + (b_base + r)*HH + q*4);
                }
                cp_commit();
                cp_wait<1>();   // chunk c complete, chunk c+1 in flight
            } else {
                cp_wait<0>();
            }
            __syncthreads();

            const float* hbuf = (c & 1) ? h_s1 : h_s0;
            const float* wB   = whh_s + c*KC;
            #pragma unroll
            for (int kk = 0; kk < 8; ++kk) {
                unsigned a[4];
                const float* Ap = hbuf + (wm + grp)*XS_STRIDE + kk*8 + thr4;
                a[0] = __float_as_uint(Ap[0]);
                a[1] = __float_as_uint(Ap[8*XS_STRIDE]);
                a[2] = __float_as_uint(Ap[4]);
                a[3] = __float_as_uint(Ap[8*XS_STRIDE + 4]);

                const float* Bp0 = wB + (wn + grp)*WHH_STRIDE + kk*8 + thr4;
                unsigned b0[2] = { __float_as_uint(Bp0[0]), __float_as_uint(Bp0[4]) };
                mma_tf32(acc0, a, b0);

                const float* Bp1 = Bp0 + 8*WHH_STRIDE;
                unsigned b1[2] = { __float_as_uint(Bp1[0]), __float_as_uint(Bp1[4]) };
                mma_tf32(acc1, a, b1);
            }
            __syncthreads();
        }

        // x-projection contribution (K = 64, operands staged in group 0, already waited)
        #pragma unroll
        for (int kk = 0; kk < 8; ++kk) {
            unsigned a[4];
            const float* Ap = x_s + (wm + grp)*XS_STRIDE + kk*8 + thr4;
            a[0] = __float_as_uint(Ap[0]);
            a[1] = __float_as_uint(Ap[8*XS_STRIDE]);
            a[2] = __float_as_uint(Ap[4]);
            a[3] = __float_as_uint(Ap[8*XS_STRIDE + 4]);

            const float* Bp0 = whx_s + (wn + grp)*XS_STRIDE + kk*8 + thr4;
            unsigned b0[2] = { __float_as_uint(Bp0[0]), __float_as_uint(Bp0[4]) };
            mma_tf32(acc0, a, b0);

            const float* Bp1 = Bp0 + 8*XS_STRIDE;
            unsigned b1[2] = { __float_as_uint(Bp1[0]), __float_as_uint(Bp1[4]) };
            mma_tf32(acc1, a, b1);
        }

        // epilogue: bias + tanh, store tf32-rounded h_new
        #pragma unroll
        for (int tile = 0; tile < 2; ++tile) {
            const float* accp = tile ? acc1 : acc0;
            #pragma unroll
            for (int i = 0; i < 4; ++i) {
                int rl = grp + ((i >> 1) << 3);
                int cl = 2*thr4 + (i & 1);
                int hl = wn + tile*8 + cl;
                float v = tanhf(accp[i] + bias_s[hl]);
                hdst[(b_base + wm + rl)*HH + h_base + hl] = to_tf32(v);
            }
        }

        // grid barrier for step t (bounded spin: deadlock -> fast wrong answer, not hang)
        __threadfence();
        __syncthreads();
        if (tid == 0) {
            atomicAdd(&g_bar[t], 1u);
            unsigned spins = 0;
            while (*((volatile unsigned*)&g_bar[t]) < GRID && ++spins < SPIN_BOUND) {
                __nanosleep(32);
            }
        }
        __threadfence();   // acquire side: order peer h writes before our next-step reads
        __syncthreads();
    }

    // ---- output epilogue: o = h_final @ Why^T + by, softmax over 10 ----
    // h_final lives in g_h[0] (512 steps -> even). Each CTA handles 2 batch rows.
    __syncthreads();
    float* logits = sm;  // reuse dynamic smem (20 floats)
    const float* hf = g_h[0];
    for (int d = warp; d < 2*DOUT; d += 8) {
        int row = d / DOUT, col = d % DOUT;
        int b = 2*cta + row;
        const float* hp = hf + (size_t)b*HH;
        const float* wp = Why + (size_t)col*HH;
        float s = 0.f;
        for (int i = lane; i < HH; i += 32)
            s += __ldcg(hp + i) * wp[i];
        #pragma unroll
        for (int o = 16; o; o >>= 1) s += __shfl_down_sync(0xffffffffu, s, o);
        if (lane == 0) logits[d] = s + by[col];
    }
    __syncthreads();
    if (tid < 2) {
        int b = 2*cta + tid;
        float mx = -1e30f;
        for (int c = 0; c < DOUT; ++c) mx = fmaxf(mx, logits[tid*DOUT + c]);
        float e[DOUT]; float sum = 0.f;
        for (int c = 0; c < DOUT; ++c) { e[c] = expf(logits[tid*DOUT + c] - mx); sum += e[c]; }
        float inv = 1.f / sum;
        for (int c = 0; c < DOUT; ++c) out[b*DOUT + c] = e[c]*inv;
    }
}

extern "C" void kernel_launch(void* const* d_in, const int* in_sizes, int n_in,
                              void* d_out, int out_size) {
    const float* x   = (const float*)d_in[0];
    const float* Whx = (const float*)d_in[1];
    const float* Whh = (const float*)d_in[2];
    const float* bh  = (const float*)d_in[3];
    const float* Why = (const float*)d_in[4];
    const float* by  = (const float*)d_in[5];
    float* out = (float*)d_out;

    cudaFuncSetAttribute(rnn_persistent_kernel,
                         cudaFuncAttributeMaxDynamicSharedMemorySize, SMEM_BYTES);

    rnn_init_kernel<<<(BB*HH + NTHREADS - 1)/NTHREADS, NTHREADS>>>();
    rnn_persistent_kernel<<<GRID, NTHREADS, SMEM_BYTES>>>(x, Whx, Whh, bh, Why, by, out);
}

// round 6
// speedup vs baseline: 1.4270x; 1.4270x over previous
#include <cuda_runtime.h>
#include <cuda_fp16.h>
#include <math.h>
#include <stdint.h>

// Problem constants
#define BB   256
#define TT   512
#define DIN  64
#define HH   1024
#define DOUT 10

// Config: 128 CTAs (4 batch-tiles x 32 h-tiles), tile 64 batch x 32 h-out
#define GRID 128
#define NTH  256
#define BT   64
#define HT   32
#define KCH  64
#define NCH  17            // 16 h-chunks + 1 x-chunk (Whx appended as cols 1024..1087)

// SMEM layout (bytes). Strides padded so 8-row ldmatrix groups hit distinct banks.
#define BSTRIDE_H 1096                     // halves per Whh row (1024 + 64 Whx + 8 pad)
#define BSTRIDE_B (BSTRIDE_H*2)            // 2192 B = 548 words == 4 mod 32
#define ASTRIDE_H 72                       // halves per h-buffer row (64 + 8 pad)
#define ASTRIDE_B (ASTRIDE_H*2)            // 144 B = 36 words == 4 mod 32
#define ABUF_B    (BT*ASTRIDE_B)           // 9216 B per buffer
#define SM_B      0
#define SM_B_SZ   (HT*BSTRIDE_B)           // 70144
#define SM_A      SM_B_SZ
#define SM_A_SZ   (3*ABUF_B)               // 27648
#define SM_BIAS   (SM_A + SM_A_SZ)         // 97792
#define SMEM_BYTES (SM_BIAS + 128)         // 97920

#define SPIN_BOUND (1u<<22)

// Global scratch (__device__ globals: allocation-free rule)
__device__ __align__(256) __half g_h[2][BB][HH];    // double-buffered hidden state fp16
__device__ __align__(256) __half g_x[TT][BB][DIN];  // x pre-converted fp16, [t][b][d]
__device__ unsigned g_bar[TT];                      // per-step barrier counters

// ---------------- helpers ----------------
__device__ __forceinline__ void cp_async16(void* sptr, const void* gptr) {
    uint32_t s = (uint32_t)__cvta_generic_to_shared(sptr);
    asm volatile("cp.async.cg.shared.global [%0], [%1], 16;" :: "r"(s), "l"(gptr));
}
__device__ __forceinline__ void cp_commit() { asm volatile("cp.async.commit_group;"); }
template<int N> __device__ __forceinline__ void cp_wait() {
    asm volatile("cp.async.wait_group %0;" :: "n"(N));
}

__device__ __forceinline__ void ldsm_x4(uint32_t& r0, uint32_t& r1, uint32_t& r2, uint32_t& r3,
                                        uint32_t addr) {
    asm volatile("ldmatrix.sync.aligned.m8n8.x4.shared.b16 {%0,%1,%2,%3}, [%4];"
                 : "=r"(r0), "=r"(r1), "=r"(r2), "=r"(r3) : "r"(addr));
}

__device__ __forceinline__ void mma16816(float* c, const uint32_t* a, uint32_t b0, uint32_t b1) {
    asm volatile(
        "mma.sync.aligned.m16n8k16.row.col.f32.f16.f16.f32 "
        "{%0,%1,%2,%3}, {%4,%5,%6,%7}, {%8,%9}, {%0,%1,%2,%3};"
        : "+f"(c[0]), "+f"(c[1]), "+f"(c[2]), "+f"(c[3])
        : "r"(a[0]), "r"(a[1]), "r"(a[2]), "r"(a[3]), "r"(b0), "r"(b1));
}

__device__ __forceinline__ float tanh_fast(float x) {
    float e = __expf(2.0f * x);
    return 1.0f - __fdividef(2.0f, e + 1.0f);
}

// ---------------- init: zero h0/bar, convert x fp32->fp16 into [t][b][d] ----------------
__global__ void rnn_init_kernel(const float* __restrict__ x) {
    int i = blockIdx.x * blockDim.x + threadIdx.x;
    if (i < BB*HH) ((__half*)g_h)[i] = __ushort_as_half((unsigned short)0);
    if (i < TT) g_bar[i] = 0u;
    for (int j = i; j < BB*TT*DIN; j += gridDim.x * blockDim.x) {
        int d = j & 63;
        int t = (j >> 6) & 511;
        int b = j >> 15;
        g_x[t][b][d] = __float2half_rn(x[j]);
    }
}

// ---------------- persistent RNN kernel ----------------
__global__ void __launch_bounds__(NTH, 1)
rnn_hmma_kernel(const float* __restrict__ Whh, const float* __restrict__ Whx,
                const float* __restrict__ bh,  const float* __restrict__ Why,
                const float* __restrict__ by,  float* __restrict__ out)
{
    extern __shared__ char sm[];
    const uint32_t smb = (uint32_t)__cvta_generic_to_shared(sm);
    const int tid = threadIdx.x, warp = tid >> 5, lane = tid & 31;
    const int cta = blockIdx.x;
    const int jb = cta & 31, ib = cta >> 5;    // 32 h-tiles x 4 b-tiles
    const int h_base = jb * HT;
    const int b_base = ib * BT;

    // ---- stage B once: Whh [32,1024] + Whx [32,64] as fp16 rows of stride 1096 ----
    __half* bs = (__half*)(sm + SM_B);
    for (int i = tid; i < HT*HH/2; i += NTH) {
        int n = i >> 9, k = (i & 511) * 2;
        const float* src = &Whh[(size_t)(h_base + n)*HH + k];
        *(__half2*)&bs[n*BSTRIDE_H + k] = __floats2half2_rn(src[0], src[1]);
    }
    for (int i = tid; i < HT*DIN/2; i += NTH) {
        int n = i >> 5, k = (i & 31) * 2;
        *(__half2*)&bs[n*BSTRIDE_H + 1024 + k] =
            __floats2half2_rn(Whx[(h_base + n)*DIN + k], Whx[(h_base + n)*DIN + k + 1]);
    }
    float* bias_s = (float*)(sm + SM_BIAS);
    if (tid < HT) bias_s[tid] = bh[h_base + tid];
    __syncthreads();

    // warp tiling: 4 m-warps (16 rows each) x 2 n-warps (16 cols each)
    const int wm = (warp >> 1) * 16;
    const int wn = (warp & 1) * 16;
    const int grp = lane >> 2, thr4 = lane & 3;

    // ldmatrix lane address components
    const int a_row  = wm + (lane & 7) + 8*((lane >> 3) & 1);
    const int a_koff = 8 * (lane >> 4);
    const int b_row  = wn + (lane & 7) + 8*(lane >> 4);
    const int b_koff = 8 * ((lane >> 3) & 1);
    const uint32_t a_lane = smb + SM_A + a_row*ASTRIDE_B + a_koff*2;
    const uint32_t b_lane = smb + SM_B + b_row*BSTRIDE_B + b_koff*2;

    bool alive = true;

    for (int t = 0; t < TT; ++t) {
        const __half* hsrc = &g_h[t & 1][0][0];

        // stage chunk c into buffer c%3 (h chunks 0..15, x chunk 16)
        auto stage = [&](int c) {
            char* dst = sm + SM_A + (c % 3) * ABUF_B;
            if (c < 16) {
                const __half* src = hsrc + (size_t)b_base*HH + c*KCH;
                for (int i = tid; i < (BT*KCH)/8; i += NTH) {
                    int r = i >> 3, q = i & 7;
                    cp_async16(dst + r*ASTRIDE_B + q*16, src + (size_t)r*HH + q*8);
                }
            } else {
                const __half* src = &g_x[t][b_base][0];
                for (int i = tid; i < (BT*KCH)/8; i += NTH) {
                    int r = i >> 3, q = i & 7;
                    cp_async16(dst + r*ASTRIDE_B + q*16, src + (size_t)r*DIN + q*8);
                }
            }
            cp_commit();
        };

        stage(0);
        stage(1);

        float acc0[4] = {0.f,0.f,0.f,0.f};
        float acc1[4] = {0.f,0.f,0.f,0.f};

        for (int c = 0; c < NCH; ++c) {
            if (c <= 14) cp_wait<1>();
            else         cp_wait<0>();
            __syncthreads();   // chunk c visible to all; buffer (c+2)%3 free to overwrite

            if (c + 2 < NCH) stage(c + 2);

            const uint32_t abase = a_lane + (c % 3) * ABUF_B;
            const uint32_t bbase = b_lane + c * (KCH * 2);
            #pragma unroll
            for (int kk = 0; kk < 4; ++kk) {
                uint32_t a0,a1,a2,a3, b0,b1,b2,b3;
                ldsm_x4(a0,a1,a2,a3, abase + kk*32);
                ldsm_x4(b0,b1,b2,b3, bbase + kk*32);
                uint32_t a[4] = {a0,a1,a2,a3};
                mma16816(acc0, a, b0, b1);
                mma16816(acc1, a, b2, b3);
            }
        }

        // ---- epilogue: bias + tanh, store h_new fp16 ----
        {
            __half* hdst = &g_h[(t + 1) & 1][0][0];
            const int r0 = b_base + wm + grp;
            #pragma unroll
            for (int tile = 0; tile < 2; ++tile) {
                const float* a = tile ? acc1 : acc0;
                const int col = h_base + wn + tile*8 + 2*thr4;
                float bl = bias_s[wn + tile*8 + 2*thr4];
                float bhp = bias_s[wn + tile*8 + 2*thr4 + 1];
                __half2 v0 = __floats2half2_rn(tanh_fast(a[0] + bl), tanh_fast(a[1] + bhp));
                __half2 v1 = __floats2half2_rn(tanh_fast(a[2] + bl), tanh_fast(a[3] + bhp));
                *(__half2*)&hdst[(size_t)r0*HH + col]       = v0;
                *(__half2*)&hdst[(size_t)(r0+8)*HH + col]   = v1;
            }
        }

        // ---- grid barrier for step t (bounded spin + latch) ----
        __threadfence();
        __syncthreads();
        if (tid == 0) {
            atomicAdd(&g_bar[t], 1u);
            if (alive) {
                unsigned spins = 0;
                while (*((volatile unsigned*)&g_bar[t]) < GRID) {
                    if (++spins >= SPIN_BOUND) { alive = false; break; }
                    __nanosleep(16);
                }
            }
        }
        __threadfence();
        __syncthreads();
    }

    // ---- output: o = h_final @ Why^T + by, softmax over 10 (2 batch rows per CTA) ----
    float* logits = (float*)(sm + SM_A);   // 20 floats; mainloop smem dead now
    const __half* hf = &g_h[0][0][0];      // TT even -> final h in buffer 0
    for (int d = warp; d < 2*DOUT; d += 8) {
        int row = d / DOUT, col = d % DOUT;
        int b = 2*cta + row;
        const __half* hp = hf + (size_t)b*HH;
        const float* wp = Why + (size_t)col*HH;
        float s = 0.f;
        for (int k = lane; k < HH; k += 32)
            s += __half2float(hp[k]) * wp[k];
        #pragma unroll
        for (int o = 16; o; o >>= 1) s += __shfl_down_sync(0xffffffffu, s, o);
        if (lane == 0) logits[d] = s + by[col];
    }
    __syncthreads();
    if (tid < 2) {
        int b = 2*cta + tid;
        float mx = -1e30f;
        for (int c = 0; c < DOUT; ++c) mx = fmaxf(mx, logits[tid*DOUT + c]);
        float e[DOUT], sum = 0.f;
        for (int c = 0; c < DOUT; ++c) { e[c] = expf(logits[tid*DOUT + c] - mx); sum += e[c]; }
        float inv = 1.f / sum;
        for (int c = 0; c < DOUT; ++c) out[b*DOUT + c] = e[c]*inv;
    }
}

extern "C" void kernel_launch(void* const* d_in, const int* in_sizes, int n_in,
                              void* d_out, int out_size) {
    const float* x   = (const float*)d_in[0];
    const float* Whx = (const float*)d_in[1];
    const float* Whh = (const float*)d_in[2];
    const float* bh  = (const float*)d_in[3];
    const float* Why = (const float*)d_in[4];
    const float* by  = (const float*)d_in[5];
    float* out = (float*)d_out;

    cudaFuncSetAttribute(rnn_hmma_kernel,
                         cudaFuncAttributeMaxDynamicSharedMemorySize, SMEM_BYTES);

    rnn_init_kernel<<<4096, 256>>>(x);
    rnn_hmma_kernel<<<GRID, NTH, SMEM_BYTES>>>(Whh, Whx, bh, Why, by, out);
}

// round 7
// speedup vs baseline: 1.7620x; 1.2347x over previous
#include <cuda_runtime.h>
#include <cuda_fp16.h>
#include <math.h>
#include <stdint.h>

// Problem constants
#define BB   256
#define TT   512
#define DIN  64
#define HH   1024
#define DOUT 10

// Config: 128 CTAs (4 batch-tiles x 32 h-tiles), tile 64 batch x 32 h-out
#define GRID 128
#define NTH  256
#define BT   64
#define HT   32
#define KCH  64
#define NCH  17            // 16 h-chunks + 1 x-chunk

// SMEM layout (bytes). Strides padded so 8-row ldmatrix groups hit distinct banks.
#define BSTRIDE_H 1096                     // halves per Whh row (1024 + 64 Whx + 8 pad)
#define BSTRIDE_B (BSTRIDE_H*2)            // 2192 B = 548 words == 4 mod 32
#define ASTRIDE_H 72                       // halves per A row (64 + 8 pad)
#define ASTRIDE_B (ASTRIDE_H*2)            // 144 B
#define ABUF_B    (BT*ASTRIDE_B)           // 9216 B per chunk buffer
#define SM_B      0
#define SM_B_SZ   (HT*BSTRIDE_B)           // 70144
#define SM_A      SM_B_SZ
#define SM_A_SZ   (NCH*ABUF_B)             // 156672
#define SM_BIAS   (SM_A + SM_A_SZ)         // 226816
#define SMEM_BYTES (SM_BIAS + 128)         // 226944  (< 232448 cap)

#define SPIN_BOUND (1u<<22)

// Global scratch (__device__ globals: allocation-free rule)
__device__ __align__(256) __half g_h[2][BB][HH];    // double-buffered hidden state fp16
__device__ __align__(256) __half g_x[TT][BB][DIN];  // x pre-converted fp16, [t][b][d]
__device__ unsigned g_bar[TT];                      // per-step barrier counters

// ---------------- helpers ----------------
__device__ __forceinline__ void cp_async16(void* sptr, const void* gptr) {
    uint32_t s = (uint32_t)__cvta_generic_to_shared(sptr);
    asm volatile("cp.async.cg.shared.global [%0], [%1], 16;" :: "r"(s), "l"(gptr));
}
__device__ __forceinline__ void cp_commit() { asm volatile("cp.async.commit_group;"); }
template<int N> __device__ __forceinline__ void cp_wait() {
    asm volatile("cp.async.wait_group %0;" :: "n"(N));
}
// switch folds to the right immediate under full unroll
__device__ __forceinline__ void cp_wait_dyn(int n) {
    switch (n) {
    case 0:  cp_wait<0>();  break;  case 1:  cp_wait<1>();  break;
    case 2:  cp_wait<2>();  break;  case 3:  cp_wait<3>();  break;
    case 4:  cp_wait<4>();  break;  case 5:  cp_wait<5>();  break;
    case 6:  cp_wait<6>();  break;  case 7:  cp_wait<7>();  break;
    case 8:  cp_wait<8>();  break;  case 9:  cp_wait<9>();  break;
    case 10: cp_wait<10>(); break;  case 11: cp_wait<11>(); break;
    case 12: cp_wait<12>(); break;  case 13: cp_wait<13>(); break;
    case 14: cp_wait<14>(); break;  case 15: cp_wait<15>(); break;
    default: cp_wait<16>(); break;
    }
}

__device__ __forceinline__ void ldsm_x4(uint32_t& r0, uint32_t& r1, uint32_t& r2, uint32_t& r3,
                                        uint32_t addr) {
    asm volatile("ldmatrix.sync.aligned.m8n8.x4.shared.b16 {%0,%1,%2,%3}, [%4];"
                 : "=r"(r0), "=r"(r1), "=r"(r2), "=r"(r3) : "r"(addr));
}

__device__ __forceinline__ void mma16816(float* c, const uint32_t* a, uint32_t b0, uint32_t b1) {
    asm volatile(
        "mma.sync.aligned.m16n8k16.row.col.f32.f16.f16.f32 "
        "{%0,%1,%2,%3}, {%4,%5,%6,%7}, {%8,%9}, {%0,%1,%2,%3};"
        : "+f"(c[0]), "+f"(c[1]), "+f"(c[2]), "+f"(c[3])
        : "r"(a[0]), "r"(a[1]), "r"(a[2]), "r"(a[3]), "r"(b0), "r"(b1));
}

__device__ __forceinline__ float tanh_fast(float x) {
    float e = __expf(2.0f * x);
    return 1.0f - __fdividef(2.0f, e + 1.0f);
}

// ---------------- init: zero h0/bar, convert x fp32->fp16 into [t][b][d] ----------------
__global__ void rnn_init_kernel(const float* __restrict__ x) {
    int i = blockIdx.x * blockDim.x + threadIdx.x;
    if (i < BB*HH) ((__half*)g_h)[i] = __ushort_as_half((unsigned short)0);
    if (i < TT) g_bar[i] = 0u;
    for (int j = i; j < BB*TT*DIN; j += gridDim.x * blockDim.x) {
        int d = j & 63;
        int t = (j >> 6) & 511;
        int b = j >> 15;
        g_x[t][b][d] = __float2half_rn(x[j]);
    }
}

// ---------------- persistent RNN kernel ----------------
__global__ void __launch_bounds__(NTH, 1)
rnn_hmma_kernel(const float* __restrict__ Whh, const float* __restrict__ Whx,
                const float* __restrict__ bh,  const float* __restrict__ Why,
                const float* __restrict__ by,  float* __restrict__ out)
{
    extern __shared__ char sm[];
    const uint32_t smb = (uint32_t)__cvta_generic_to_shared(sm);
    const int tid = threadIdx.x, warp = tid >> 5, lane = tid & 31;
    const int cta = blockIdx.x;
    const int jb = cta & 31, ib = cta >> 5;    // 32 h-tiles x 4 b-tiles
    const int h_base = jb * HT;
    const int b_base = ib * BT;

    // ---- stage B once: Whh [32,1024] + Whx [32,64] as fp16 rows of stride 1096 ----
    __half* bs = (__half*)(sm + SM_B);
    for (int i = tid; i < HT*HH/2; i += NTH) {
        int n = i >> 9, k = (i & 511) * 2;
        const float* src = &Whh[(size_t)(h_base + n)*HH + k];
        *(__half2*)&bs[n*BSTRIDE_H + k] = __floats2half2_rn(src[0], src[1]);
    }
    for (int i = tid; i < HT*DIN/2; i += NTH) {
        int n = i >> 5, k = (i & 31) * 2;
        *(__half2*)&bs[n*BSTRIDE_H + 1024 + k] =
            __floats2half2_rn(Whx[(h_base + n)*DIN + k], Whx[(h_base + n)*DIN + k + 1]);
    }
    float* bias_s = (float*)(sm + SM_BIAS);
    if (tid < HT) bias_s[tid] = bh[h_base + tid];
    __syncthreads();

    // warp tiling: 4 m-warps (16 rows each) x 2 n-warps (16 cols each)
    const int wp   = warp >> 1;       // pair id 0..3 (m-tile)
    const int wm   = wp * 16;
    const int wn   = (warp & 1) * 16;
    const int grp  = lane >> 2, thr4 = lane & 3;
    const int ptid = tid & 63;        // thread id within the 64-thread pair

    // ldmatrix lane address components
    const int a_row  = wm + (lane & 7) + 8*((lane >> 3) & 1);
    const int a_koff = 8 * (lane >> 4);
    const int b_row  = wn + (lane & 7) + 8*(lane >> 4);
    const int b_koff = 8 * ((lane >> 3) & 1);
    const uint32_t a_lane = smb + SM_A + a_row*ASTRIDE_B + a_koff*2;
    const uint32_t b_lane = smb + SM_B + b_row*BSTRIDE_B + b_koff*2;

    bool alive = true;

    for (int t = 0; t < TT; ++t) {
        const __half* hsrc = &g_h[t & 1][0][0];

        // ---- stage ALL 17 chunks up-front: each pair stages its own 16 A rows ----
        // pair wp handles rows [wm, wm+16); 16 rows x 8 x16B per chunk / 64 thr = 2 ops/thr
        {
            const int r = wm + (ptid >> 3);       // row handled (2 rows per thread: +8)
            const int q = ptid & 7;               // 16B piece within chunk row
            #pragma unroll
            for (int c = 0; c < NCH; ++c) {
                char* dst0 = sm + SM_A + c*ABUF_B + r*ASTRIDE_B + q*16;
                if (c < 16) {
                    const __half* s0 = hsrc + (size_t)(b_base + r)*HH + c*KCH + q*8;
                    cp_async16(dst0,                  s0);
                    cp_async16(dst0 + 8*ASTRIDE_B,    s0 + 8*HH);
                } else {
                    const __half* s0 = &g_x[t][b_base + r][q*8];
                    cp_async16(dst0,                  s0);
                    cp_async16(dst0 + 8*ASTRIDE_B,    s0 + 8*DIN);
                }
                cp_commit();
            }
        }

        float acc0[4] = {0.f,0.f,0.f,0.f};
        float acc1[4] = {0.f,0.f,0.f,0.f};

        // ---- compute: consume chunks as they land; pair-local sync only ----
        #pragma unroll
        for (int c = 0; c < NCH; ++c) {
            cp_wait_dyn(16 - c);                       // own groups <= c complete
            asm volatile("bar.sync %0, 64;" :: "r"(wp + 1) : "memory");  // pair staged

            const uint32_t abase = a_lane + c * ABUF_B;
            const uint32_t bbase = b_lane + c * (KCH * 2);
            #pragma unroll
            for (int kk = 0; kk < 4; ++kk) {
                uint32_t a0,a1,a2,a3, b0,b1,b2,b3;
                ldsm_x4(a0,a1,a2,a3, abase + kk*32);
                ldsm_x4(b0,b1,b2,b3, bbase + kk*32);
                uint32_t a[4] = {a0,a1,a2,a3};
                mma16816(acc0, a, b0, b1);
                mma16816(acc1, a, b2, b3);
            }
        }

        // ---- epilogue: bias + tanh, store h_new fp16 (per-warp independent) ----
        {
            __half* hdst = &g_h[(t + 1) & 1][0][0];
            const int r0 = b_base + wm + grp;
            #pragma unroll
            for (int tile = 0; tile < 2; ++tile) {
                const float* a = tile ? acc1 : acc0;
                const int col = h_base + wn + tile*8 + 2*thr4;
                float bl  = bias_s[wn + tile*8 + 2*thr4];
                float bhp = bias_s[wn + tile*8 + 2*thr4 + 1];
                __half2 v0 = __floats2half2_rn(tanh_fast(a[0] + bl), tanh_fast(a[1] + bhp));
                __half2 v1 = __floats2half2_rn(tanh_fast(a[2] + bl), tanh_fast(a[3] + bhp));
                *(__half2*)&hdst[(size_t)r0*HH + col]     = v0;
                *(__half2*)&hdst[(size_t)(r0+8)*HH + col] = v1;
            }
        }

        // ---- grid barrier for step t (bounded spin + latch) ----
        __threadfence();
        __syncthreads();
        if (tid == 0) {
            atomicAdd(&g_bar[t], 1u);
            if (alive) {
                unsigned spins = 0;
                while (*((volatile unsigned*)&g_bar[t]) < GRID) {
                    if (++spins >= SPIN_BOUND) { alive = false; break; }
                    __nanosleep(8);
                }
            }
        }
        __threadfence();
        __syncthreads();
    }

    // ---- output: o = h_final @ Why^T + by, softmax over 10 (2 batch rows per CTA) ----
    float* logits = (float*)(sm + SM_A);   // 20 floats; mainloop smem dead now
    const __half* hf = &g_h[0][0][0];      // TT even -> final h in buffer 0
    for (int d = warp; d < 2*DOUT; d += 8) {
        int row = d / DOUT, col = d % DOUT;
        int b = 2*cta + row;
        const __half* hp = hf + (size_t)b*HH;
        const float* wpw = Why + (size_t)col*HH;
        float s = 0.f;
        for (int k = lane; k < HH; k += 32)
            s += __half2float(hp[k]) * wpw[k];
        #pragma unroll
        for (int o = 16; o; o >>= 1) s += __shfl_down_sync(0xffffffffu, s, o);
        if (lane == 0) logits[d] = s + by[col];
    }
    __syncthreads();
    if (tid < 2) {
        int b = 2*cta + tid;
        float mx = -1e30f;
        for (int c = 0; c < DOUT; ++c) mx = fmaxf(mx, logits[tid*DOUT + c]);
        float e[DOUT], sum = 0.f;
        for (int c = 0; c < DOUT; ++c) { e[c] = expf(logits[tid*DOUT + c] - mx); sum += e[c]; }
        float inv = 1.f / sum;
        for (int c = 0; c < DOUT; ++c) out[b*DOUT + c] = e[c]*inv;
    }
}

extern "C" void kernel_launch(void* const* d_in, const int* in_sizes, int n_in,
                              void* d_out, int out_size) {
    const float* x   = (const float*)d_in[0];
    const float* Whx = (const float*)d_in[1];
    const float* Whh = (const float*)d_in[2];
    const float* bh  = (const float*)d_in[3];
    const float* Why = (const float*)d_in[4];
    const float* by  = (const float*)d_in[5];
    float* out = (float*)d_out;

    cudaFuncSetAttribute(rnn_hmma_kernel,
                         cudaFuncAttributeMaxDynamicSharedMemorySize, SMEM_BYTES);

    rnn_init_kernel<<<4096, 256>>>(x);
    rnn_hmma_kernel<<<GRID, NTH, SMEM_BYTES>>>(Whh, Whx, bh, Why, by, out);
}